// round 15
// baseline (speedup 1.0000x reference)
#include <cuda_runtime.h>
#include <cuda_bf16.h>
#include <cstdint>

#define NB    127
#define KD    1024
#define ND    256
#define NITER 2                 // loop NS updates (3 total Y updates with fused first)
#define MSZ   ((size_t)ND * ND)

static __device__ __align__(256) __nv_bfloat16 g_Xt[(size_t)NB * ND * KD]; // [b][i][k]
static __device__ __align__(256) float          g_G [(size_t)NB * MSZ];    // Gram
static __device__ __align__(256) __nv_bfloat16  g_A [(size_t)NB * MSZ];
static __device__ __align__(256) __nv_bfloat16  g_Y [2][(size_t)NB * MSZ];
static __device__ __align__(256) __nv_bfloat16  g_Z [2][(size_t)NB * MSZ];
static __device__ __align__(256) __nv_bfloat16  g_T [(size_t)NB * MSZ];
static __device__ float g_c[NB];
static __device__ float g_corr[NB];     // accumulates 0.5*<Z, A - Y Y^T>
static __device__ float g_S[NB];

// ------------------------------------------------------------------ helpers
__device__ __forceinline__ uint32_t sptr(const void* p) {
    uint32_t a;
    asm("{ .reg .u64 t; cvta.to.shared.u64 t, %1; cvt.u32.u64 %0, t; }"
        : "=r"(a) : "l"(p));
    return a;
}
#define CP_ASYNC(dst, src) \
    asm volatile("cp.async.cg.shared.global [%0], [%1], 16;" :: "r"(dst), "l"(src))
#define CP_COMMIT() asm volatile("cp.async.commit_group;" ::: "memory")
#define CP_WAIT(n)  asm volatile("cp.async.wait_group %0;" :: "n"(n) : "memory")

__device__ __forceinline__ void ldsm4(uint32_t* r, uint32_t a) {
    asm volatile("ldmatrix.sync.aligned.m8n8.x4.shared.b16 {%0,%1,%2,%3}, [%4];"
                 : "=r"(r[0]), "=r"(r[1]), "=r"(r[2]), "=r"(r[3]) : "r"(a));
}
__device__ __forceinline__ void mma16816(float* d, const uint32_t* a, const uint32_t* b) {
    asm volatile("mma.sync.aligned.m16n8k16.row.col.f32.bf16.bf16.f32 "
                 "{%0,%1,%2,%3}, {%4,%5,%6,%7}, {%8,%9}, {%0,%1,%2,%3};"
                 : "+f"(d[0]), "+f"(d[1]), "+f"(d[2]), "+f"(d[3])
                 : "r"(a[0]), "r"(a[1]), "r"(a[2]), "r"(a[3]), "r"(b[0]), "r"(b[1]));
}

__device__ __forceinline__ float warp_sum(float v) {
#pragma unroll
    for (int o = 16; o > 0; o >>= 1) v += __shfl_xor_sync(0xffffffffu, v, o);
    return v;
}
__device__ float block_sum(float v, float* red) {
    int lane = threadIdx.x & 31, w = threadIdx.x >> 5;
    int nw = (blockDim.x + 31) >> 5;
    v = warp_sum(v);
    if (lane == 0) red[w] = v;
    __syncthreads();
    if (w == 0) {
        float t = (lane < nw) ? red[lane] : 0.f;
        t = warp_sum(t);
        if (lane == 0) red[0] = t;
    }
    __syncthreads();
    float r = red[0];
    __syncthreads();
    return r;
}

// ------------------------------------------------------------------ convert: X fp32 -> Xt bf16 (transposed), 64k x 128i tile per CTA
__global__ __launch_bounds__(256)
void convert_kernel(const float* __restrict__ X) {
    __shared__ float tile[64][129];
    int b = blockIdx.z;
    int k0 = blockIdx.x * 64, i0 = blockIdx.y * 128;
    int tid = threadIdx.x;
    const float* Xb = X + (size_t)b * KD * ND;
#pragma unroll
    for (int p = 0; p < 8; p++) {
        int id = tid + p * 256;
        int r = id >> 5, c4 = id & 31;
        float4 v = *(const float4*)(Xb + (size_t)(k0 + r) * ND + i0 + c4 * 4);
        tile[r][c4 * 4 + 0] = v.x;
        tile[r][c4 * 4 + 1] = v.y;
        tile[r][c4 * 4 + 2] = v.z;
        tile[r][c4 * 4 + 3] = v.w;
    }
    __syncthreads();
#pragma unroll
    for (int p = 0; p < 4; p++) {
        int id = tid + p * 256;
        int i = id >> 3, kg = id & 7;       // 8 consecutive k per store
        uint32_t pk[4];
#pragma unroll
        for (int j = 0; j < 4; j++) {
            __nv_bfloat162 h = __floats2bfloat162_rn(tile[kg * 8 + 2 * j][i],
                                                     tile[kg * 8 + 2 * j + 1][i]);
            pk[j] = *(uint32_t*)&h;
        }
        *(uint4*)(g_Xt + ((size_t)b * ND + i0 + i) * KD + k0 + kg * 8) =
            make_uint4(pk[0], pk[1], pk[2], pk[3]);
    }
}

// ------------------------------------------------------------------ fragment addressing (8 warps: 2x4 grid, 64x32 out per warp)
struct FragAddr {
    uint32_t baseA[4], xorA[4], baseB[2], xorB[2];
    int wm, wn, lane;
    __device__ void init(int tid) {
        lane = tid & 31;
        int wid = tid >> 5;
        wm = wid >> 2; wn = wid & 3;
        int mx = lane >> 3;
#pragma unroll
        for (int mi = 0; mi < 4; mi++) {
            int row = wm * 64 + mi * 16 + (mx & 1) * 8 + (lane & 7);
            baseA[mi] = (uint32_t)(row * 128 + (mx >> 1) * 16);
            xorA[mi]  = (uint32_t)((row & 7) << 4);
        }
#pragma unroll
        for (int nj = 0; nj < 2; nj++) {
            int row = wn * 32 + nj * 16 + (mx >> 1) * 8 + (lane & 7);
            baseB[nj] = (uint32_t)(row * 128 + (mx & 1) * 16);
            xorB[nj]  = (uint32_t)((row & 7) << 4);
        }
    }
};

__device__ __forceinline__ void mma_chunk(const FragAddr& fa, uint32_t aB, uint32_t bB,
                                          float acc[4][4][4]) {
#pragma unroll
    for (int ks = 0; ks < 4; ks++) {
        uint32_t afr[4][4], bfr[4][2];
#pragma unroll
        for (int mi = 0; mi < 4; mi++)
            ldsm4(afr[mi], aB + ((fa.baseA[mi] + ks * 32) ^ fa.xorA[mi]));
#pragma unroll
        for (int nj = 0; nj < 2; nj++) {
            uint32_t r4[4];
            ldsm4(r4, bB + ((fa.baseB[nj] + ks * 32) ^ fa.xorB[nj]));
            bfr[nj * 2][0] = r4[0]; bfr[nj * 2][1] = r4[1];
            bfr[nj * 2 + 1][0] = r4[2]; bfr[nj * 2 + 1][1] = r4[3];
        }
#pragma unroll
        for (int mi = 0; mi < 4; mi++)
#pragma unroll
            for (int ni = 0; ni < 4; ni++)
                mma16816(acc[mi][ni], afr[mi], bfr[ni]);
    }
}

// ------------------------------------------------------------------ symmetric GEMM: D = A * B^T, 3-stage cp.async, 256 threads.
// Lower-tri CTA tiles {(0,0),(1,0),(1,1)}; (1,0) mirrors into (0,1).
// Diagonal tiles with A==B load only one operand and alias it.
// grid.x = 3 (single) or 6 (dual).
// MODE 0: store fp32 ; 1: store (3I-D)/2 bf16 ; 2: store D bf16 ;
// MODE 3: no store — atomicAdd(0.5*w*(<Z,A> - <Z,D>)) into g_corr[b]; Z via O0/O1.
#define SMEM_GEMM 98304   // 3 stages x 16KB x 2 operands

template<int KK, int MODE>
__global__ __launch_bounds__(256, 2)
void gemm_t(const __nv_bfloat16* __restrict__ A0, const __nv_bfloat16* __restrict__ B0,
            void* __restrict__ O0,
            const __nv_bfloat16* __restrict__ A1, const __nv_bfloat16* __restrict__ B1,
            void* __restrict__ O1, size_t aStr, size_t bStr)
{
    extern __shared__ char smraw[];
    const int b = blockIdx.y;
    const int second = (blockIdx.x >= 3) ? 1 : 0;
    const int tix = blockIdx.x - second * 3;
    const int mt = (tix + 1) >> 1, nt = tix >> 1;
    const bool mirror = (tix == 1);

    const __nv_bfloat16* A = (second ? A1 : A0) + (size_t)b * aStr + (size_t)(mt * 128) * KK;
    const __nv_bfloat16* B = (second ? B1 : B0) + (size_t)b * bStr + (size_t)(nt * 128) * KK;
    const bool dup = (mt == nt) && (A == B);   // identical tile: load once, alias

    uint32_t sA = sptr(smraw);           // 3 x 16KB
    uint32_t sB = sA + 49152;            // 3 x 16KB

    const int tid = threadIdx.x;
    FragAddr fa; fa.init(tid);

    float acc[4][4][4];
#pragma unroll
    for (int i = 0; i < 4; i++)
#pragma unroll
        for (int j = 0; j < 4; j++)
#pragma unroll
            for (int r = 0; r < 4; r++) acc[i][j][r] = 0.f;

    constexpr int nc = KK / 64;

    auto issue = [&](int c) {
        uint32_t s = (uint32_t)(c % 3) * 16384u;
        const __nv_bfloat16* Ag = A + c * 64;
        const __nv_bfloat16* Bg = B + c * 64;
#pragma unroll
        for (int q = 0; q < 4; q++) {
            int id = tid + q * 256;
            int r = id >> 3, u = id & 7;
            uint32_t off = (uint32_t)(r * 128 + u * 16);
            off ^= (off >> 3) & 0x70u;
            CP_ASYNC(sA + s + off, Ag + (size_t)r * KK + u * 8);
            if (!dup) CP_ASYNC(sB + s + off, Bg + (size_t)r * KK + u * 8);
        }
        CP_COMMIT();
    };

    issue(0);
    if (nc > 1) issue(1);
#pragma unroll 4
    for (int c = 0; c < nc; c++) {
        if (c + 1 < nc) { CP_WAIT(1); }
        else            { CP_WAIT(0); }
        __syncthreads();
        if (c + 2 < nc) issue(c + 2);
        uint32_t s = (uint32_t)(c % 3) * 16384u;
        mma_chunk(fa, sA + s, dup ? (sA + s) : (sB + s), acc);
    }

    int gmb = mt * 128 + fa.wm * 64;
    int gnb = nt * 128 + fa.wn * 32;
    if (MODE == 0) {
        float* Og = (float*)(second ? O1 : O0) + (size_t)b * MSZ;
#pragma unroll
        for (int mi = 0; mi < 4; mi++)
#pragma unroll
            for (int ni = 0; ni < 4; ni++) {
                int gm = gmb + mi * 16 + (fa.lane >> 2);
                int gn = gnb + ni * 8 + (fa.lane & 3) * 2;
                float d0 = acc[mi][ni][0], d1 = acc[mi][ni][1];
                float d2 = acc[mi][ni][2], d3 = acc[mi][ni][3];
                *(float2*)(Og + (size_t)gm * ND + gn) = make_float2(d0, d1);
                *(float2*)(Og + (size_t)(gm + 8) * ND + gn) = make_float2(d2, d3);
                if (mirror) {
                    Og[(size_t)gn * ND + gm] = d0;
                    Og[(size_t)(gn + 1) * ND + gm] = d1;
                    Og[(size_t)gn * ND + gm + 8] = d2;
                    Og[(size_t)(gn + 1) * ND + gm + 8] = d3;
                }
            }
    } else if (MODE == 3) {
        const __nv_bfloat16* Zg = (const __nv_bfloat16*)(second ? O1 : O0) + (size_t)b * MSZ;
        const __nv_bfloat16* Ag = g_A + (size_t)b * MSZ;
        float dot = 0.f;
#pragma unroll
        for (int mi = 0; mi < 4; mi++)
#pragma unroll
            for (int ni = 0; ni < 4; ni++) {
                int gm = gmb + mi * 16 + (fa.lane >> 2);
                int gn = gnb + ni * 8 + (fa.lane & 3) * 2;
                float2 z0 = __bfloat1622float2(*(const __nv_bfloat162*)(Zg + (size_t)gm * ND + gn));
                float2 z1 = __bfloat1622float2(*(const __nv_bfloat162*)(Zg + (size_t)(gm + 8) * ND + gn));
                float2 a0 = __bfloat1622float2(*(const __nv_bfloat162*)(Ag + (size_t)gm * ND + gn));
                float2 a1 = __bfloat1622float2(*(const __nv_bfloat162*)(Ag + (size_t)(gm + 8) * ND + gn));
                dot += z0.x * (a0.x - acc[mi][ni][0]) + z0.y * (a0.y - acc[mi][ni][1])
                     + z1.x * (a1.x - acc[mi][ni][2]) + z1.y * (a1.y - acc[mi][ni][3]);
            }
        __shared__ float red[32];
        float tot = block_sum(dot, red);
        if (tid == 0) atomicAdd(&g_corr[b], 0.5f * (mirror ? 2.f : 1.f) * tot);
    } else {
        __nv_bfloat16* Og = (__nv_bfloat16*)(second ? O1 : O0) + (size_t)b * MSZ;
#pragma unroll
        for (int mi = 0; mi < 4; mi++)
#pragma unroll
            for (int ni = 0; ni < 4; ni++) {
                int gm = gmb + mi * 16 + (fa.lane >> 2);
                int gn = gnb + ni * 8 + (fa.lane & 3) * 2;
                float d0 = acc[mi][ni][0], d1 = acc[mi][ni][1];
                float d2 = acc[mi][ni][2], d3 = acc[mi][ni][3];
                if (MODE == 1) {
                    d0 = (((gn     == gm    ) ? 3.f : 0.f) - d0) * 0.5f;
                    d1 = (((gn + 1 == gm    ) ? 3.f : 0.f) - d1) * 0.5f;
                    d2 = (((gn     == gm + 8) ? 3.f : 0.f) - d2) * 0.5f;
                    d3 = (((gn + 1 == gm + 8) ? 3.f : 0.f) - d3) * 0.5f;
                }
                __nv_bfloat16 h0 = __float2bfloat16(d0), h1 = __float2bfloat16(d1);
                __nv_bfloat16 h2 = __float2bfloat16(d2), h3 = __float2bfloat16(d3);
                __nv_bfloat162 p0, p1;
                p0.x = h0; p0.y = h1;
                p1.x = h2; p1.y = h3;
                *(__nv_bfloat162*)(Og + (size_t)gm * ND + gn) = p0;
                *(__nv_bfloat162*)(Og + (size_t)(gm + 8) * ND + gn) = p1;
                if (mirror) {
                    Og[(size_t)gn * ND + gm] = h0;
                    Og[(size_t)(gn + 1) * ND + gm] = h1;
                    Og[(size_t)gn * ND + gm + 8] = h2;
                    Og[(size_t)(gn + 1) * ND + gm + 8] = h3;
                }
            }
    }
}

// ------------------------------------------------------------------ power iteration -> c = 0.63 * rayleigh
__global__ void powc_kernel() {
    __shared__ float v[ND];
    __shared__ float red[32];
    int b = blockIdx.x, t = threadIdx.x;
    const float* G = g_G + (size_t)b * MSZ;
    v[t] = 1.f;
    __syncthreads();
    float w = 0.f;
    for (int it = 0; it < 5; it++) {
        const float4* row = (const float4*)(G + (size_t)t * ND);
        float a0 = 0.f;
#pragma unroll 8
        for (int j = 0; j < 64; j++) {
            float4 g = row[j];
            a0 += g.x * v[4 * j] + g.y * v[4 * j + 1] + g.z * v[4 * j + 2] + g.w * v[4 * j + 3];
        }
        w = a0;
        __syncthreads();
        if (it < 4) { v[t] = w; __syncthreads(); }
    }
    float vw = block_sum(v[t] * w, red);
    float vv = block_sum(v[t] * v[t], red);
    if (t == 0) g_c[b] = 0.63f * (vw / vv);   // a in [~0.18, ~1.65]
}

// ------------------------------------------------------------------ setup: A=G/c bf16, T0=(3I-A)/2, Z1=T0; zero g_corr
__global__ void setup_kernel() {
    int b = blockIdx.y;
    if (blockIdx.x == 0 && threadIdx.x == 0) g_corr[b] = 0.f;
    float inv = 1.f / g_c[b];
    const float* G = g_G + (size_t)b * MSZ;
    __nv_bfloat16* Ab = g_A + (size_t)b * MSZ;
    __nv_bfloat16* T0 = g_T + (size_t)b * MSZ;
    __nv_bfloat16* Z1 = g_Z[1] + (size_t)b * MSZ;
    int col4 = threadIdx.x & 63;
    int rsub = threadIdx.x >> 6;
#pragma unroll
    for (int j = 0; j < 8; j++) {
        int r = blockIdx.x * 32 + j * 4 + rsub;
        float4 g = *(const float4*)(G + (size_t)r * ND + col4 * 4);
        float a0 = g.x * inv, a1 = g.y * inv, a2 = g.z * inv, a3 = g.w * inv;
        int c0 = col4 * 4;
        float t0 = (((c0     == r) ? 3.f : 0.f) - a0) * 0.5f;
        float t1 = (((c0 + 1 == r) ? 3.f : 0.f) - a1) * 0.5f;
        float t2 = (((c0 + 2 == r) ? 3.f : 0.f) - a2) * 0.5f;
        float t3 = (((c0 + 3 == r) ? 3.f : 0.f) - a3) * 0.5f;
        __nv_bfloat162 ha0 = __floats2bfloat162_rn(a0, a1);
        __nv_bfloat162 ha1 = __floats2bfloat162_rn(a2, a3);
        __nv_bfloat162 ht0 = __floats2bfloat162_rn(t0, t1);
        __nv_bfloat162 ht1 = __floats2bfloat162_rn(t2, t3);
        uint2 ua = make_uint2(*(uint32_t*)&ha0, *(uint32_t*)&ha1);
        uint2 ut = make_uint2(*(uint32_t*)&ht0, *(uint32_t*)&ht1);
        *(uint2*)(Ab + (size_t)r * ND + c0) = ua;
        *(uint2*)(T0 + (size_t)r * ND + c0) = ut;
        *(uint2*)(Z1 + (size_t)r * ND + c0) = ut;
    }
}

// ------------------------------------------------------------------ refine: S = sqrt(c)*(trY + corr)
__global__ void refine_kernel(const __nv_bfloat16* __restrict__ Y) {
    __shared__ float red[32];
    int b = blockIdx.x, t = threadIdx.x;
    float trY = __bfloat162float(Y[(size_t)b * MSZ + (size_t)t * ND + t]);
    float sY = block_sum(trY, red);
    if (t == 0) g_S[b] = sqrtf(g_c[b]) * (sY + g_corr[b]);
}

__global__ void final_kernel(float* __restrict__ out) {
    __shared__ float red[32];
    float v = 0.f;
    for (int i = threadIdx.x; i < NB; i += blockDim.x) v += g_S[i];
    float tot = block_sum(v, red);
    if (threadIdx.x == 0) out[0] = 1e-4f * (tot / (float)NB);
}

// ------------------------------------------------------------------
extern "C" void kernel_launch(void* const* d_in, const int* in_sizes, int n_in,
                              void* d_out, int out_size) {
    (void)in_sizes; (void)n_in; (void)out_size;
    const float* cores = (const float*)d_in[0];
    float* out = (float*)d_out;

    cudaFuncSetAttribute(gemm_t<1024, 0>, cudaFuncAttributeMaxDynamicSharedMemorySize, SMEM_GEMM);
    cudaFuncSetAttribute(gemm_t<256, 1>,  cudaFuncAttributeMaxDynamicSharedMemorySize, SMEM_GEMM);
    cudaFuncSetAttribute(gemm_t<256, 2>,  cudaFuncAttributeMaxDynamicSharedMemorySize, SMEM_GEMM);
    cudaFuncSetAttribute(gemm_t<256, 3>,  cudaFuncAttributeMaxDynamicSharedMemorySize, SMEM_GEMM);

    void *xt_, *gg_, *aa_, *y_, *z_, *tt_;
    cudaGetSymbolAddress(&xt_, g_Xt);
    cudaGetSymbolAddress(&gg_, g_G);
    cudaGetSymbolAddress(&aa_, g_A);
    cudaGetSymbolAddress(&y_,  g_Y);
    cudaGetSymbolAddress(&z_,  g_Z);
    cudaGetSymbolAddress(&tt_, g_T);
    const __nv_bfloat16* Xt = (const __nv_bfloat16*)xt_;
    float* G = (float*)gg_;
    const __nv_bfloat16* Ab = (const __nv_bfloat16*)aa_;
    __nv_bfloat16* Y[2] = { (__nv_bfloat16*)y_, (__nv_bfloat16*)y_ + NB * MSZ };
    __nv_bfloat16* Z[2] = { (__nv_bfloat16*)z_, (__nv_bfloat16*)z_ + NB * MSZ };
    __nv_bfloat16* T = (__nv_bfloat16*)tt_;

    convert_kernel<<<dim3(KD / 64, ND / 128, NB), 256>>>(cores);

    // G = Xt * Xt^T (fp32, symmetric 3 tiles + mirror; diag tiles single-load)
    gemm_t<1024, 0><<<dim3(3, NB), 256, SMEM_GEMM>>>(Xt, Xt, G, Xt, Xt, G,
                                                     (size_t)ND * KD, (size_t)ND * KD);
    powc_kernel<<<NB, 256>>>();
    setup_kernel<<<dim3(8, NB), 256>>>();      // A, T0, Z1; zero g_corr

    // Y1 = A * T0^T
    gemm_t<256, 2><<<dim3(3, NB), 256, SMEM_GEMM>>>(Ab, T, Y[1], Ab, T, Y[1], MSZ, MSZ);

    int cur = 1;
    for (int t = 0; t < NITER; t++) {
        gemm_t<256, 1><<<dim3(3, NB), 256, SMEM_GEMM>>>(Z[cur], Y[cur], T,
                                                        Z[cur], Y[cur], T, MSZ, MSZ);
        if (t < NITER - 1) {
            gemm_t<256, 2><<<dim3(6, NB), 256, SMEM_GEMM>>>(Y[cur], T, Y[cur ^ 1],
                                                            T, Z[cur], Z[cur ^ 1], MSZ, MSZ);
            cur ^= 1;
        } else {
            // last update: Y only (Z lags one step; fp32 correction absorbs it)
            gemm_t<256, 2><<<dim3(3, NB), 256, SMEM_GEMM>>>(Y[cur], T, Y[cur ^ 1],
                                                            Y[cur], T, Y[cur ^ 1], MSZ, MSZ);
        }
    }
    int yf = cur ^ 1, zf = cur;

    // corr += 0.5*<Z, A - Y Y^T> fused into the GEMM epilogue (diag tiles single-load)
    gemm_t<256, 3><<<dim3(3, NB), 256, SMEM_GEMM>>>(Y[yf], Y[yf], Z[zf],
                                                    Y[yf], Y[yf], Z[zf], MSZ, MSZ);
    refine_kernel<<<NB, 256>>>(Y[yf]);
    final_kernel<<<1, 128>>>(out);
}

// round 16
// speedup vs baseline: 1.0531x; 1.0531x over previous
#include <cuda_runtime.h>
#include <cuda_bf16.h>
#include <cstdint>

#define NB    127
#define KD    1024
#define ND    256
#define NITER 2                 // loop NS updates (3 total Y updates with fused first)
#define MSZ   ((size_t)ND * ND)

static __device__ __align__(256) __nv_bfloat16 g_Xt[(size_t)NB * ND * KD]; // [b][i][k]
static __device__ __align__(256) float          g_G [(size_t)NB * MSZ];    // Gram
static __device__ __align__(256) __nv_bfloat16  g_A [(size_t)NB * MSZ];
static __device__ __align__(256) __nv_bfloat16  g_Y [2][(size_t)NB * MSZ];
static __device__ __align__(256) __nv_bfloat16  g_Z [2][(size_t)NB * MSZ];
static __device__ __align__(256) __nv_bfloat16  g_T [(size_t)NB * MSZ];
static __device__ float g_c[NB];
static __device__ float g_corr[NB];     // accumulates trY + 0.5*<Z, A - Y Y^T>
static __device__ float g_S[NB];

// ------------------------------------------------------------------ helpers
__device__ __forceinline__ uint32_t sptr(const void* p) {
    uint32_t a;
    asm("{ .reg .u64 t; cvta.to.shared.u64 t, %1; cvt.u32.u64 %0, t; }"
        : "=r"(a) : "l"(p));
    return a;
}
#define CP_ASYNC(dst, src) \
    asm volatile("cp.async.cg.shared.global [%0], [%1], 16;" :: "r"(dst), "l"(src))
#define CP_COMMIT() asm volatile("cp.async.commit_group;" ::: "memory")
#define CP_WAIT(n)  asm volatile("cp.async.wait_group %0;" :: "n"(n) : "memory")

__device__ __forceinline__ void ldsm4(uint32_t* r, uint32_t a) {
    asm volatile("ldmatrix.sync.aligned.m8n8.x4.shared.b16 {%0,%1,%2,%3}, [%4];"
                 : "=r"(r[0]), "=r"(r[1]), "=r"(r[2]), "=r"(r[3]) : "r"(a));
}
__device__ __forceinline__ void mma16816(float* d, const uint32_t* a, const uint32_t* b) {
    asm volatile("mma.sync.aligned.m16n8k16.row.col.f32.bf16.bf16.f32 "
                 "{%0,%1,%2,%3}, {%4,%5,%6,%7}, {%8,%9}, {%0,%1,%2,%3};"
                 : "+f"(d[0]), "+f"(d[1]), "+f"(d[2]), "+f"(d[3])
                 : "r"(a[0]), "r"(a[1]), "r"(a[2]), "r"(a[3]), "r"(b[0]), "r"(b[1]));
}

__device__ __forceinline__ float warp_sum(float v) {
#pragma unroll
    for (int o = 16; o > 0; o >>= 1) v += __shfl_xor_sync(0xffffffffu, v, o);
    return v;
}
__device__ float block_sum(float v, float* red) {
    int lane = threadIdx.x & 31, w = threadIdx.x >> 5;
    int nw = (blockDim.x + 31) >> 5;
    v = warp_sum(v);
    if (lane == 0) red[w] = v;
    __syncthreads();
    if (w == 0) {
        float t = (lane < nw) ? red[lane] : 0.f;
        t = warp_sum(t);
        if (lane == 0) red[0] = t;
    }
    __syncthreads();
    float r = red[0];
    __syncthreads();
    return r;
}

// ------------------------------------------------------------------ convert: X fp32 -> Xt bf16 (transposed), 64x64 tile per CTA
__global__ __launch_bounds__(256)
void convert_kernel(const float* __restrict__ X) {
    __shared__ float tile[64][65];
    int b = blockIdx.z;
    int k0 = blockIdx.x * 64, i0 = blockIdx.y * 64;
    int tid = threadIdx.x;
    const float* Xb = X + (size_t)b * KD * ND;
#pragma unroll
    for (int p = 0; p < 4; p++) {
        int id = tid + p * 256;
        int r = id >> 4, c4 = id & 15;
        float4 v = *(const float4*)(Xb + (size_t)(k0 + r) * ND + i0 + c4 * 4);
        tile[r][c4 * 4 + 0] = v.x;
        tile[r][c4 * 4 + 1] = v.y;
        tile[r][c4 * 4 + 2] = v.z;
        tile[r][c4 * 4 + 3] = v.w;
    }
    __syncthreads();
#pragma unroll
    for (int p = 0; p < 2; p++) {
        int id = tid + p * 256;
        int i = id >> 3, kg = id & 7;       // 8 consecutive k per store
        uint32_t pk[4];
#pragma unroll
        for (int j = 0; j < 4; j++) {
            __nv_bfloat162 h = __floats2bfloat162_rn(tile[kg * 8 + 2 * j][i],
                                                     tile[kg * 8 + 2 * j + 1][i]);
            pk[j] = *(uint32_t*)&h;
        }
        *(uint4*)(g_Xt + ((size_t)b * ND + i0 + i) * KD + k0 + kg * 8) =
            make_uint4(pk[0], pk[1], pk[2], pk[3]);
    }
}

// ------------------------------------------------------------------ fragment addressing (8 warps: 2x4 grid, 64x32 out per warp)
struct FragAddr {
    uint32_t baseA[4], xorA[4], baseB[2], xorB[2];
    int wm, wn, lane;
    __device__ void init(int tid) {
        lane = tid & 31;
        int wid = tid >> 5;
        wm = wid >> 2; wn = wid & 3;
        int mx = lane >> 3;
#pragma unroll
        for (int mi = 0; mi < 4; mi++) {
            int row = wm * 64 + mi * 16 + (mx & 1) * 8 + (lane & 7);
            baseA[mi] = (uint32_t)(row * 128 + (mx >> 1) * 16);
            xorA[mi]  = (uint32_t)((row & 7) << 4);
        }
#pragma unroll
        for (int nj = 0; nj < 2; nj++) {
            int row = wn * 32 + nj * 16 + (mx >> 1) * 8 + (lane & 7);
            baseB[nj] = (uint32_t)(row * 128 + (mx & 1) * 16);
            xorB[nj]  = (uint32_t)((row & 7) << 4);
        }
    }
};

__device__ __forceinline__ void mma_chunk(const FragAddr& fa, uint32_t aB, uint32_t bB,
                                          float acc[4][4][4]) {
#pragma unroll
    for (int ks = 0; ks < 4; ks++) {
        uint32_t afr[4][4], bfr[4][2];
#pragma unroll
        for (int mi = 0; mi < 4; mi++)
            ldsm4(afr[mi], aB + ((fa.baseA[mi] + ks * 32) ^ fa.xorA[mi]));
#pragma unroll
        for (int nj = 0; nj < 2; nj++) {
            uint32_t r4[4];
            ldsm4(r4, bB + ((fa.baseB[nj] + ks * 32) ^ fa.xorB[nj]));
            bfr[nj * 2][0] = r4[0]; bfr[nj * 2][1] = r4[1];
            bfr[nj * 2 + 1][0] = r4[2]; bfr[nj * 2 + 1][1] = r4[3];
        }
#pragma unroll
        for (int mi = 0; mi < 4; mi++)
#pragma unroll
            for (int ni = 0; ni < 4; ni++)
                mma16816(acc[mi][ni], afr[mi], bfr[ni]);
    }
}

// ------------------------------------------------------------------ symmetric GEMM: D = A * B^T, 3-stage cp.async, 256 threads.
// Lower-tri CTA tiles {(0,0),(1,0),(1,1)}; (1,0) mirrors into (0,1).
// Diagonal tiles with A==B load only one operand and alias it.
// grid.x = 3 (single) or 6 (dual).
// MODE 0: store fp32 ; 1: store (3I-D)/2 bf16 ; 2: store D bf16 ;
// MODE 3: no store — atomicAdd(trY_part + 0.5*w*(<Z,A> - <Z,D>)) into g_corr[b].
#define SMEM_GEMM 98304   // 3 stages x 16KB x 2 operands

template<int KK, int MODE>
__global__ __launch_bounds__(256, 2)
void gemm_t(const __nv_bfloat16* __restrict__ A0, const __nv_bfloat16* __restrict__ B0,
            void* __restrict__ O0,
            const __nv_bfloat16* __restrict__ A1, const __nv_bfloat16* __restrict__ B1,
            void* __restrict__ O1, size_t aStr, size_t bStr)
{
    extern __shared__ char smraw[];
    const int b = blockIdx.y;
    const int second = (blockIdx.x >= 3) ? 1 : 0;
    const int tix = blockIdx.x - second * 3;
    const int mt = (tix + 1) >> 1, nt = tix >> 1;
    const bool mirror = (tix == 1);

    const __nv_bfloat16* A = (second ? A1 : A0) + (size_t)b * aStr + (size_t)(mt * 128) * KK;
    const __nv_bfloat16* B = (second ? B1 : B0) + (size_t)b * bStr + (size_t)(nt * 128) * KK;
    const bool dup = (mt == nt) && (A == B);   // identical tile: load once, alias

    uint32_t sA = sptr(smraw);           // 3 x 16KB
    uint32_t sB = sA + 49152;            // 3 x 16KB

    const int tid = threadIdx.x;
    FragAddr fa; fa.init(tid);

    float acc[4][4][4];
#pragma unroll
    for (int i = 0; i < 4; i++)
#pragma unroll
        for (int j = 0; j < 4; j++)
#pragma unroll
            for (int r = 0; r < 4; r++) acc[i][j][r] = 0.f;

    constexpr int nc = KK / 64;

    auto issue = [&](int c) {
        uint32_t s = (uint32_t)(c % 3) * 16384u;
        const __nv_bfloat16* Ag = A + c * 64;
        const __nv_bfloat16* Bg = B + c * 64;
#pragma unroll
        for (int q = 0; q < 4; q++) {
            int id = tid + q * 256;
            int r = id >> 3, u = id & 7;
            uint32_t off = (uint32_t)(r * 128 + u * 16);
            off ^= (off >> 3) & 0x70u;
            CP_ASYNC(sA + s + off, Ag + (size_t)r * KK + u * 8);
            if (!dup) CP_ASYNC(sB + s + off, Bg + (size_t)r * KK + u * 8);
        }
        CP_COMMIT();
    };

    issue(0);
    if (nc > 1) issue(1);
#pragma unroll 4
    for (int c = 0; c < nc; c++) {
        if (c + 1 < nc) { CP_WAIT(1); }
        else            { CP_WAIT(0); }
        __syncthreads();
        if (c + 2 < nc) issue(c + 2);
        uint32_t s = (uint32_t)(c % 3) * 16384u;
        mma_chunk(fa, sA + s, dup ? (sA + s) : (sB + s), acc);
    }

    int gmb = mt * 128 + fa.wm * 64;
    int gnb = nt * 128 + fa.wn * 32;
    if (MODE == 0) {
        float* Og = (float*)(second ? O1 : O0) + (size_t)b * MSZ;
#pragma unroll
        for (int mi = 0; mi < 4; mi++)
#pragma unroll
            for (int ni = 0; ni < 4; ni++) {
                int gm = gmb + mi * 16 + (fa.lane >> 2);
                int gn = gnb + ni * 8 + (fa.lane & 3) * 2;
                float d0 = acc[mi][ni][0], d1 = acc[mi][ni][1];
                float d2 = acc[mi][ni][2], d3 = acc[mi][ni][3];
                *(float2*)(Og + (size_t)gm * ND + gn) = make_float2(d0, d1);
                *(float2*)(Og + (size_t)(gm + 8) * ND + gn) = make_float2(d2, d3);
                if (mirror) {
                    Og[(size_t)gn * ND + gm] = d0;
                    Og[(size_t)(gn + 1) * ND + gm] = d1;
                    Og[(size_t)gn * ND + gm + 8] = d2;
                    Og[(size_t)(gn + 1) * ND + gm + 8] = d3;
                }
            }
    } else if (MODE == 3) {
        const __nv_bfloat16* Zg = (const __nv_bfloat16*)(second ? O1 : O0) + (size_t)b * MSZ;
        const __nv_bfloat16* Ag = g_A + (size_t)b * MSZ;
        float dot = 0.f;
#pragma unroll
        for (int mi = 0; mi < 4; mi++)
#pragma unroll
            for (int ni = 0; ni < 4; ni++) {
                int gm = gmb + mi * 16 + (fa.lane >> 2);
                int gn = gnb + ni * 8 + (fa.lane & 3) * 2;
                float2 z0 = __bfloat1622float2(*(const __nv_bfloat162*)(Zg + (size_t)gm * ND + gn));
                float2 z1 = __bfloat1622float2(*(const __nv_bfloat162*)(Zg + (size_t)(gm + 8) * ND + gn));
                float2 a0 = __bfloat1622float2(*(const __nv_bfloat162*)(Ag + (size_t)gm * ND + gn));
                float2 a1 = __bfloat1622float2(*(const __nv_bfloat162*)(Ag + (size_t)(gm + 8) * ND + gn));
                dot += z0.x * (a0.x - acc[mi][ni][0]) + z0.y * (a0.y - acc[mi][ni][1])
                     + z1.x * (a1.x - acc[mi][ni][2]) + z1.y * (a1.y - acc[mi][ni][3]);
            }
        // fold tr(Y) in on diagonal tiles: weight 2 pre-sum cancels the 0.5 post-sum
        if ((mt == nt) && tid < 128) {
            float yd = __bfloat162float(A[(size_t)tid * KK + mt * 128 + tid]);
            dot += 2.f * yd;
        }
        __shared__ float red[32];
        float tot = block_sum(dot, red);
        if (tid == 0) atomicAdd(&g_corr[b], 0.5f * (mirror ? 2.f : 1.f) * tot);
    } else {
        __nv_bfloat16* Og = (__nv_bfloat16*)(second ? O1 : O0) + (size_t)b * MSZ;
#pragma unroll
        for (int mi = 0; mi < 4; mi++)
#pragma unroll
            for (int ni = 0; ni < 4; ni++) {
                int gm = gmb + mi * 16 + (fa.lane >> 2);
                int gn = gnb + ni * 8 + (fa.lane & 3) * 2;
                float d0 = acc[mi][ni][0], d1 = acc[mi][ni][1];
                float d2 = acc[mi][ni][2], d3 = acc[mi][ni][3];
                if (MODE == 1) {
                    d0 = (((gn     == gm    ) ? 3.f : 0.f) - d0) * 0.5f;
                    d1 = (((gn + 1 == gm    ) ? 3.f : 0.f) - d1) * 0.5f;
                    d2 = (((gn     == gm + 8) ? 3.f : 0.f) - d2) * 0.5f;
                    d3 = (((gn + 1 == gm + 8) ? 3.f : 0.f) - d3) * 0.5f;
                }
                __nv_bfloat16 h0 = __float2bfloat16(d0), h1 = __float2bfloat16(d1);
                __nv_bfloat16 h2 = __float2bfloat16(d2), h3 = __float2bfloat16(d3);
                __nv_bfloat162 p0, p1;
                p0.x = h0; p0.y = h1;
                p1.x = h2; p1.y = h3;
                *(__nv_bfloat162*)(Og + (size_t)gm * ND + gn) = p0;
                *(__nv_bfloat162*)(Og + (size_t)(gm + 8) * ND + gn) = p1;
                if (mirror) {
                    Og[(size_t)gn * ND + gm] = h0;
                    Og[(size_t)(gn + 1) * ND + gm] = h1;
                    Og[(size_t)gn * ND + gm + 8] = h2;
                    Og[(size_t)(gn + 1) * ND + gm + 8] = h3;
                }
            }
    }
}

// ------------------------------------------------------------------ power iteration -> c = 0.63 * rayleigh
__global__ void powc_kernel() {
    __shared__ float v[ND];
    __shared__ float red[32];
    int b = blockIdx.x, t = threadIdx.x;
    const float* G = g_G + (size_t)b * MSZ;
    v[t] = 1.f;
    __syncthreads();
    float w = 0.f;
    for (int it = 0; it < 5; it++) {
        const float4* row = (const float4*)(G + (size_t)t * ND);
        float a0 = 0.f;
#pragma unroll 8
        for (int j = 0; j < 64; j++) {
            float4 g = row[j];
            a0 += g.x * v[4 * j] + g.y * v[4 * j + 1] + g.z * v[4 * j + 2] + g.w * v[4 * j + 3];
        }
        w = a0;
        __syncthreads();
        if (it < 4) { v[t] = w; __syncthreads(); }
    }
    float vw = block_sum(v[t] * w, red);
    float vv = block_sum(v[t] * v[t], red);
    if (t == 0) g_c[b] = 0.63f * (vw / vv);   // a in [~0.18, ~1.65]
}

// ------------------------------------------------------------------ setup: A=G/c bf16, T0=(3I-A)/2, Z1=T0; zero g_corr
__global__ void setup_kernel() {
    int b = blockIdx.y;
    if (blockIdx.x == 0 && threadIdx.x == 0) g_corr[b] = 0.f;
    float inv = 1.f / g_c[b];
    const float* G = g_G + (size_t)b * MSZ;
    __nv_bfloat16* Ab = g_A + (size_t)b * MSZ;
    __nv_bfloat16* T0 = g_T + (size_t)b * MSZ;
    __nv_bfloat16* Z1 = g_Z[1] + (size_t)b * MSZ;
    int col4 = threadIdx.x & 63;
    int rsub = threadIdx.x >> 6;
#pragma unroll
    for (int j = 0; j < 8; j++) {
        int r = blockIdx.x * 32 + j * 4 + rsub;
        float4 g = *(const float4*)(G + (size_t)r * ND + col4 * 4);
        float a0 = g.x * inv, a1 = g.y * inv, a2 = g.z * inv, a3 = g.w * inv;
        int c0 = col4 * 4;
        float t0 = (((c0     == r) ? 3.f : 0.f) - a0) * 0.5f;
        float t1 = (((c0 + 1 == r) ? 3.f : 0.f) - a1) * 0.5f;
        float t2 = (((c0 + 2 == r) ? 3.f : 0.f) - a2) * 0.5f;
        float t3 = (((c0 + 3 == r) ? 3.f : 0.f) - a3) * 0.5f;
        __nv_bfloat162 ha0 = __floats2bfloat162_rn(a0, a1);
        __nv_bfloat162 ha1 = __floats2bfloat162_rn(a2, a3);
        __nv_bfloat162 ht0 = __floats2bfloat162_rn(t0, t1);
        __nv_bfloat162 ht1 = __floats2bfloat162_rn(t2, t3);
        uint2 ua = make_uint2(*(uint32_t*)&ha0, *(uint32_t*)&ha1);
        uint2 ut = make_uint2(*(uint32_t*)&ht0, *(uint32_t*)&ht1);
        *(uint2*)(Ab + (size_t)r * ND + c0) = ua;
        *(uint2*)(T0 + (size_t)r * ND + c0) = ut;
        *(uint2*)(Z1 + (size_t)r * ND + c0) = ut;
    }
}

// ------------------------------------------------------------------ final: out = 1e-4 * mean_b sqrt(c_b) * corr_b
__global__ void final_kernel(float* __restrict__ out) {
    __shared__ float red[32];
    float v = 0.f;
    for (int i = threadIdx.x; i < NB; i += blockDim.x)
        v += sqrtf(g_c[i]) * g_corr[i];
    float tot = block_sum(v, red);
    if (threadIdx.x == 0) out[0] = 1e-4f * (tot / (float)NB);
}

// ------------------------------------------------------------------
extern "C" void kernel_launch(void* const* d_in, const int* in_sizes, int n_in,
                              void* d_out, int out_size) {
    (void)in_sizes; (void)n_in; (void)out_size;
    const float* cores = (const float*)d_in[0];
    float* out = (float*)d_out;

    cudaFuncSetAttribute(gemm_t<1024, 0>, cudaFuncAttributeMaxDynamicSharedMemorySize, SMEM_GEMM);
    cudaFuncSetAttribute(gemm_t<256, 1>,  cudaFuncAttributeMaxDynamicSharedMemorySize, SMEM_GEMM);
    cudaFuncSetAttribute(gemm_t<256, 2>,  cudaFuncAttributeMaxDynamicSharedMemorySize, SMEM_GEMM);
    cudaFuncSetAttribute(gemm_t<256, 3>,  cudaFuncAttributeMaxDynamicSharedMemorySize, SMEM_GEMM);

    void *xt_, *gg_, *aa_, *y_, *z_, *tt_;
    cudaGetSymbolAddress(&xt_, g_Xt);
    cudaGetSymbolAddress(&gg_, g_G);
    cudaGetSymbolAddress(&aa_, g_A);
    cudaGetSymbolAddress(&y_,  g_Y);
    cudaGetSymbolAddress(&z_,  g_Z);
    cudaGetSymbolAddress(&tt_, g_T);
    const __nv_bfloat16* Xt = (const __nv_bfloat16*)xt_;
    float* G = (float*)gg_;
    const __nv_bfloat16* Ab = (const __nv_bfloat16*)aa_;
    __nv_bfloat16* Y[2] = { (__nv_bfloat16*)y_, (__nv_bfloat16*)y_ + NB * MSZ };
    __nv_bfloat16* Z[2] = { (__nv_bfloat16*)z_, (__nv_bfloat16*)z_ + NB * MSZ };
    __nv_bfloat16* T = (__nv_bfloat16*)tt_;

    convert_kernel<<<dim3(KD / 64, ND / 64, NB), 256>>>(cores);

    // G = Xt * Xt^T (fp32, symmetric 3 tiles + mirror; diag tiles single-load)
    gemm_t<1024, 0><<<dim3(3, NB), 256, SMEM_GEMM>>>(Xt, Xt, G, Xt, Xt, G,
                                                     (size_t)ND * KD, (size_t)ND * KD);
    powc_kernel<<<NB, 256>>>();
    setup_kernel<<<dim3(8, NB), 256>>>();      // A, T0, Z1; zero g_corr

    // Y1 = A * T0^T
    gemm_t<256, 2><<<dim3(3, NB), 256, SMEM_GEMM>>>(Ab, T, Y[1], Ab, T, Y[1], MSZ, MSZ);

    int cur = 1;
    for (int t = 0; t < NITER; t++) {
        gemm_t<256, 1><<<dim3(3, NB), 256, SMEM_GEMM>>>(Z[cur], Y[cur], T,
                                                        Z[cur], Y[cur], T, MSZ, MSZ);
        if (t < NITER - 1) {
            gemm_t<256, 2><<<dim3(6, NB), 256, SMEM_GEMM>>>(Y[cur], T, Y[cur ^ 1],
                                                            T, Z[cur], Z[cur ^ 1], MSZ, MSZ);
            cur ^= 1;
        } else {
            // last update: Y only (Z lags one step; fp32 correction absorbs it)
            gemm_t<256, 2><<<dim3(3, NB), 256, SMEM_GEMM>>>(Y[cur], T, Y[cur ^ 1],
                                                            Y[cur], T, Y[cur ^ 1], MSZ, MSZ);
        }
    }
    int yf = cur ^ 1, zf = cur;

    // corr += trY + 0.5*<Z, A - Y Y^T> fused into the GEMM epilogue (refine folded away)
    gemm_t<256, 3><<<dim3(3, NB), 256, SMEM_GEMM>>>(Y[yf], Y[yf], Z[zf],
                                                    Y[yf], Y[yf], Z[zf], MSZ, MSZ);
    final_kernel<<<1, 128>>>(out);
}

// round 17
// speedup vs baseline: 1.1251x; 1.0684x over previous
#include <cuda_runtime.h>
#include <cuda_bf16.h>
#include <cstdint>

#define NB    127
#define KD    1024
#define ND    256
#define MSZ   ((size_t)ND * ND)

static __device__ __align__(256) __nv_bfloat16 g_Xt[(size_t)NB * ND * KD]; // [b][i][k]
static __device__ __align__(256) float          g_G [(size_t)NB * MSZ];    // Gram
static __device__ __align__(256) __nv_bfloat16  g_A [(size_t)NB * MSZ];
static __device__ __align__(256) __nv_bfloat16  g_Y [2][(size_t)NB * MSZ];
static __device__ __align__(256) __nv_bfloat16  g_Z [2][(size_t)NB * MSZ];
static __device__ __align__(256) __nv_bfloat16  g_T [(size_t)NB * MSZ];
static __device__ float g_c[NB];
static __device__ float g_corr[NB];     // accumulates trY + 0.5*<Z, A - Y Y^T>

// ------------------------------------------------------------------ helpers
__device__ __forceinline__ uint32_t sptr(const void* p) {
    uint32_t a;
    asm("{ .reg .u64 t; cvta.to.shared.u64 t, %1; cvt.u32.u64 %0, t; }"
        : "=r"(a) : "l"(p));
    return a;
}
#define CP_ASYNC(dst, src) \
    asm volatile("cp.async.cg.shared.global [%0], [%1], 16;" :: "r"(dst), "l"(src))
#define CP_COMMIT() asm volatile("cp.async.commit_group;" ::: "memory")
#define CP_WAIT(n)  asm volatile("cp.async.wait_group %0;" :: "n"(n) : "memory")

__device__ __forceinline__ void ldsm4(uint32_t* r, uint32_t a) {
    asm volatile("ldmatrix.sync.aligned.m8n8.x4.shared.b16 {%0,%1,%2,%3}, [%4];"
                 : "=r"(r[0]), "=r"(r[1]), "=r"(r[2]), "=r"(r[3]) : "r"(a));
}
__device__ __forceinline__ void mma16816(float* d, const uint32_t* a, const uint32_t* b) {
    asm volatile("mma.sync.aligned.m16n8k16.row.col.f32.bf16.bf16.f32 "
                 "{%0,%1,%2,%3}, {%4,%5,%6,%7}, {%8,%9}, {%0,%1,%2,%3};"
                 : "+f"(d[0]), "+f"(d[1]), "+f"(d[2]), "+f"(d[3])
                 : "r"(a[0]), "r"(a[1]), "r"(a[2]), "r"(a[3]), "r"(b[0]), "r"(b[1]));
}

__device__ __forceinline__ float warp_sum(float v) {
#pragma unroll
    for (int o = 16; o > 0; o >>= 1) v += __shfl_xor_sync(0xffffffffu, v, o);
    return v;
}
__device__ float block_sum(float v, float* red) {
    int lane = threadIdx.x & 31, w = threadIdx.x >> 5;
    int nw = (blockDim.x + 31) >> 5;
    v = warp_sum(v);
    if (lane == 0) red[w] = v;
    __syncthreads();
    if (w == 0) {
        float t = (lane < nw) ? red[lane] : 0.f;
        t = warp_sum(t);
        if (lane == 0) red[0] = t;
    }
    __syncthreads();
    float r = red[0];
    __syncthreads();
    return r;
}

// ------------------------------------------------------------------ convert: X fp32 -> Xt bf16 (transposed), 64x64 tile per CTA
__global__ __launch_bounds__(256)
void convert_kernel(const float* __restrict__ X) {
    __shared__ float tile[64][65];
    int b = blockIdx.z;
    int k0 = blockIdx.x * 64, i0 = blockIdx.y * 64;
    int tid = threadIdx.x;
    const float* Xb = X + (size_t)b * KD * ND;
#pragma unroll
    for (int p = 0; p < 4; p++) {
        int id = tid + p * 256;
        int r = id >> 4, c4 = id & 15;
        float4 v = *(const float4*)(Xb + (size_t)(k0 + r) * ND + i0 + c4 * 4);
        tile[r][c4 * 4 + 0] = v.x;
        tile[r][c4 * 4 + 1] = v.y;
        tile[r][c4 * 4 + 2] = v.z;
        tile[r][c4 * 4 + 3] = v.w;
    }
    __syncthreads();
#pragma unroll
    for (int p = 0; p < 2; p++) {
        int id = tid + p * 256;
        int i = id >> 3, kg = id & 7;       // 8 consecutive k per store
        uint32_t pk[4];
#pragma unroll
        for (int j = 0; j < 4; j++) {
            __nv_bfloat162 h = __floats2bfloat162_rn(tile[kg * 8 + 2 * j][i],
                                                     tile[kg * 8 + 2 * j + 1][i]);
            pk[j] = *(uint32_t*)&h;
        }
        *(uint4*)(g_Xt + ((size_t)b * ND + i0 + i) * KD + k0 + kg * 8) =
            make_uint4(pk[0], pk[1], pk[2], pk[3]);
    }
}

// ------------------------------------------------------------------ fragment addressing (8 warps: 2x4 grid, 64x32 out per warp)
struct FragAddr {
    uint32_t baseA[4], xorA[4], baseB[2], xorB[2];
    int wm, wn, lane;
    __device__ void init(int tid) {
        lane = tid & 31;
        int wid = tid >> 5;
        wm = wid >> 2; wn = wid & 3;
        int mx = lane >> 3;
#pragma unroll
        for (int mi = 0; mi < 4; mi++) {
            int row = wm * 64 + mi * 16 + (mx & 1) * 8 + (lane & 7);
            baseA[mi] = (uint32_t)(row * 128 + (mx >> 1) * 16);
            xorA[mi]  = (uint32_t)((row & 7) << 4);
        }
#pragma unroll
        for (int nj = 0; nj < 2; nj++) {
            int row = wn * 32 + nj * 16 + (mx >> 1) * 8 + (lane & 7);
            baseB[nj] = (uint32_t)(row * 128 + (mx & 1) * 16);
            xorB[nj]  = (uint32_t)((row & 7) << 4);
        }
    }
};

__device__ __forceinline__ void mma_chunk(const FragAddr& fa, uint32_t aB, uint32_t bB,
                                          float acc[4][4][4]) {
#pragma unroll
    for (int ks = 0; ks < 4; ks++) {
        uint32_t afr[4][4], bfr[4][2];
#pragma unroll
        for (int mi = 0; mi < 4; mi++)
            ldsm4(afr[mi], aB + ((fa.baseA[mi] + ks * 32) ^ fa.xorA[mi]));
#pragma unroll
        for (int nj = 0; nj < 2; nj++) {
            uint32_t r4[4];
            ldsm4(r4, bB + ((fa.baseB[nj] + ks * 32) ^ fa.xorB[nj]));
            bfr[nj * 2][0] = r4[0]; bfr[nj * 2][1] = r4[1];
            bfr[nj * 2 + 1][0] = r4[2]; bfr[nj * 2 + 1][1] = r4[3];
        }
#pragma unroll
        for (int mi = 0; mi < 4; mi++)
#pragma unroll
            for (int ni = 0; ni < 4; ni++)
                mma16816(acc[mi][ni], afr[mi], bfr[ni]);
    }
}

// ------------------------------------------------------------------ symmetric GEMM: D = A * B^T, 3-stage cp.async, 256 threads.
// Lower-tri CTA tiles {(0,0),(1,0),(1,1)}; (1,0) mirrors into (0,1).
// Diagonal tiles with A==B load only one operand and alias it.
// grid.x = 3 (single) or 6 (dual).
// MODE 0: store fp32 ; 1: store (3I-D)/2 bf16 ; 2: store D bf16 ;
// MODE 3: no store — atomicAdd(trY_part + 0.5*w*(<Z,A> - <Z,D>)) into g_corr[b].
#define SMEM_GEMM 98304   // 3 stages x 16KB x 2 operands

template<int KK, int MODE>
__global__ __launch_bounds__(256, 2)
void gemm_t(const __nv_bfloat16* __restrict__ A0, const __nv_bfloat16* __restrict__ B0,
            void* __restrict__ O0,
            const __nv_bfloat16* __restrict__ A1, const __nv_bfloat16* __restrict__ B1,
            void* __restrict__ O1, size_t aStr, size_t bStr)
{
    extern __shared__ char smraw[];
    const int b = blockIdx.y;
    const int second = (blockIdx.x >= 3) ? 1 : 0;
    const int tix = blockIdx.x - second * 3;
    const int mt = (tix + 1) >> 1, nt = tix >> 1;
    const bool mirror = (tix == 1);

    const __nv_bfloat16* A = (second ? A1 : A0) + (size_t)b * aStr + (size_t)(mt * 128) * KK;
    const __nv_bfloat16* B = (second ? B1 : B0) + (size_t)b * bStr + (size_t)(nt * 128) * KK;
    const bool dup = (mt == nt) && (A == B);   // identical tile: load once, alias

    uint32_t sA = sptr(smraw);           // 3 x 16KB
    uint32_t sB = sA + 49152;            // 3 x 16KB

    const int tid = threadIdx.x;
    FragAddr fa; fa.init(tid);

    float acc[4][4][4];
#pragma unroll
    for (int i = 0; i < 4; i++)
#pragma unroll
        for (int j = 0; j < 4; j++)
#pragma unroll
            for (int r = 0; r < 4; r++) acc[i][j][r] = 0.f;

    constexpr int nc = KK / 64;

    auto issue = [&](int c) {
        uint32_t s = (uint32_t)(c % 3) * 16384u;
        const __nv_bfloat16* Ag = A + c * 64;
        const __nv_bfloat16* Bg = B + c * 64;
#pragma unroll
        for (int q = 0; q < 4; q++) {
            int id = tid + q * 256;
            int r = id >> 3, u = id & 7;
            uint32_t off = (uint32_t)(r * 128 + u * 16);
            off ^= (off >> 3) & 0x70u;
            CP_ASYNC(sA + s + off, Ag + (size_t)r * KK + u * 8);
            if (!dup) CP_ASYNC(sB + s + off, Bg + (size_t)r * KK + u * 8);
        }
        CP_COMMIT();
    };

    issue(0);
    if (nc > 1) issue(1);
#pragma unroll 4
    for (int c = 0; c < nc; c++) {
        if (c + 1 < nc) { CP_WAIT(1); }
        else            { CP_WAIT(0); }
        __syncthreads();
        if (c + 2 < nc) issue(c + 2);
        uint32_t s = (uint32_t)(c % 3) * 16384u;
        mma_chunk(fa, sA + s, dup ? (sA + s) : (sB + s), acc);
    }

    int gmb = mt * 128 + fa.wm * 64;
    int gnb = nt * 128 + fa.wn * 32;
    if (MODE == 0) {
        float* Og = (float*)(second ? O1 : O0) + (size_t)b * MSZ;
#pragma unroll
        for (int mi = 0; mi < 4; mi++)
#pragma unroll
            for (int ni = 0; ni < 4; ni++) {
                int gm = gmb + mi * 16 + (fa.lane >> 2);
                int gn = gnb + ni * 8 + (fa.lane & 3) * 2;
                float d0 = acc[mi][ni][0], d1 = acc[mi][ni][1];
                float d2 = acc[mi][ni][2], d3 = acc[mi][ni][3];
                *(float2*)(Og + (size_t)gm * ND + gn) = make_float2(d0, d1);
                *(float2*)(Og + (size_t)(gm + 8) * ND + gn) = make_float2(d2, d3);
                if (mirror) {
                    Og[(size_t)gn * ND + gm] = d0;
                    Og[(size_t)(gn + 1) * ND + gm] = d1;
                    Og[(size_t)gn * ND + gm + 8] = d2;
                    Og[(size_t)(gn + 1) * ND + gm + 8] = d3;
                }
            }
    } else if (MODE == 3) {
        const __nv_bfloat16* Zg = (const __nv_bfloat16*)(second ? O1 : O0) + (size_t)b * MSZ;
        const __nv_bfloat16* Ag = g_A + (size_t)b * MSZ;
        float dot = 0.f;
#pragma unroll
        for (int mi = 0; mi < 4; mi++)
#pragma unroll
            for (int ni = 0; ni < 4; ni++) {
                int gm = gmb + mi * 16 + (fa.lane >> 2);
                int gn = gnb + ni * 8 + (fa.lane & 3) * 2;
                float2 z0 = __bfloat1622float2(*(const __nv_bfloat162*)(Zg + (size_t)gm * ND + gn));
                float2 z1 = __bfloat1622float2(*(const __nv_bfloat162*)(Zg + (size_t)(gm + 8) * ND + gn));
                float2 a0 = __bfloat1622float2(*(const __nv_bfloat162*)(Ag + (size_t)gm * ND + gn));
                float2 a1 = __bfloat1622float2(*(const __nv_bfloat162*)(Ag + (size_t)(gm + 8) * ND + gn));
                dot += z0.x * (a0.x - acc[mi][ni][0]) + z0.y * (a0.y - acc[mi][ni][1])
                     + z1.x * (a1.x - acc[mi][ni][2]) + z1.y * (a1.y - acc[mi][ni][3]);
            }
        // fold tr(Y) in on diagonal tiles: weight 2 pre-sum cancels the 0.5 post-sum
        if ((mt == nt) && tid < 128) {
            float yd = __bfloat162float(A[(size_t)tid * KK + mt * 128 + tid]);
            dot += 2.f * yd;
        }
        __shared__ float red[32];
        float tot = block_sum(dot, red);
        if (tid == 0) atomicAdd(&g_corr[b], 0.5f * (mirror ? 2.f : 1.f) * tot);
    } else {
        __nv_bfloat16* Og = (__nv_bfloat16*)(second ? O1 : O0) + (size_t)b * MSZ;
#pragma unroll
        for (int mi = 0; mi < 4; mi++)
#pragma unroll
            for (int ni = 0; ni < 4; ni++) {
                int gm = gmb + mi * 16 + (fa.lane >> 2);
                int gn = gnb + ni * 8 + (fa.lane & 3) * 2;
                float d0 = acc[mi][ni][0], d1 = acc[mi][ni][1];
                float d2 = acc[mi][ni][2], d3 = acc[mi][ni][3];
                if (MODE == 1) {
                    d0 = (((gn     == gm    ) ? 3.f : 0.f) - d0) * 0.5f;
                    d1 = (((gn + 1 == gm    ) ? 3.f : 0.f) - d1) * 0.5f;
                    d2 = (((gn     == gm + 8) ? 3.f : 0.f) - d2) * 0.5f;
                    d3 = (((gn + 1 == gm + 8) ? 3.f : 0.f) - d3) * 0.5f;
                }
                __nv_bfloat16 h0 = __float2bfloat16(d0), h1 = __float2bfloat16(d1);
                __nv_bfloat16 h2 = __float2bfloat16(d2), h3 = __float2bfloat16(d3);
                __nv_bfloat162 p0, p1;
                p0.x = h0; p0.y = h1;
                p1.x = h2; p1.y = h3;
                *(__nv_bfloat162*)(Og + (size_t)gm * ND + gn) = p0;
                *(__nv_bfloat162*)(Og + (size_t)(gm + 8) * ND + gn) = p1;
                if (mirror) {
                    Og[(size_t)gn * ND + gm] = h0;
                    Og[(size_t)(gn + 1) * ND + gm] = h1;
                    Og[(size_t)gn * ND + gm + 8] = h2;
                    Og[(size_t)(gn + 1) * ND + gm + 8] = h3;
                }
            }
    }
}

// ------------------------------------------------------------------ power iteration (3 sweeps) -> c = 0.63 * rayleigh
__global__ void powc_kernel() {
    __shared__ float v[ND];
    __shared__ float red[32];
    int b = blockIdx.x, t = threadIdx.x;
    const float* G = g_G + (size_t)b * MSZ;
    v[t] = 1.f;
    __syncthreads();
    float w = 0.f;
    for (int it = 0; it < 3; it++) {
        const float4* row = (const float4*)(G + (size_t)t * ND);
        float a0 = 0.f;
#pragma unroll 8
        for (int j = 0; j < 64; j++) {
            float4 g = row[j];
            a0 += g.x * v[4 * j] + g.y * v[4 * j + 1] + g.z * v[4 * j + 2] + g.w * v[4 * j + 3];
        }
        w = a0;
        __syncthreads();
        if (it < 2) { v[t] = w; __syncthreads(); }
    }
    float vw = block_sum(v[t] * w, red);
    float vv = block_sum(v[t] * v[t], red);
    if (t == 0) g_c[b] = 0.63f * (vw / vv);
}

// ------------------------------------------------------------------ setup: A=G/c bf16, T0=(3I-A)/2 (no Z1 copy); zero g_corr
__global__ void setup_kernel() {
    int b = blockIdx.y;
    if (blockIdx.x == 0 && threadIdx.x == 0) g_corr[b] = 0.f;
    float inv = 1.f / g_c[b];
    const float* G = g_G + (size_t)b * MSZ;
    __nv_bfloat16* Ab = g_A + (size_t)b * MSZ;
    __nv_bfloat16* T0 = g_T + (size_t)b * MSZ;
    int col4 = threadIdx.x & 63;
    int rsub = threadIdx.x >> 6;
#pragma unroll
    for (int j = 0; j < 8; j++) {
        int r = blockIdx.x * 32 + j * 4 + rsub;
        float4 g = *(const float4*)(G + (size_t)r * ND + col4 * 4);
        float a0 = g.x * inv, a1 = g.y * inv, a2 = g.z * inv, a3 = g.w * inv;
        int c0 = col4 * 4;
        float t0 = (((c0     == r) ? 3.f : 0.f) - a0) * 0.5f;
        float t1 = (((c0 + 1 == r) ? 3.f : 0.f) - a1) * 0.5f;
        float t2 = (((c0 + 2 == r) ? 3.f : 0.f) - a2) * 0.5f;
        float t3 = (((c0 + 3 == r) ? 3.f : 0.f) - a3) * 0.5f;
        __nv_bfloat162 ha0 = __floats2bfloat162_rn(a0, a1);
        __nv_bfloat162 ha1 = __floats2bfloat162_rn(a2, a3);
        __nv_bfloat162 ht0 = __floats2bfloat162_rn(t0, t1);
        __nv_bfloat162 ht1 = __floats2bfloat162_rn(t2, t3);
        uint2 ua = make_uint2(*(uint32_t*)&ha0, *(uint32_t*)&ha1);
        uint2 ut = make_uint2(*(uint32_t*)&ht0, *(uint32_t*)&ht1);
        *(uint2*)(Ab + (size_t)r * ND + c0) = ua;
        *(uint2*)(T0 + (size_t)r * ND + c0) = ut;
    }
}

// ------------------------------------------------------------------ final: out = 1e-4 * mean_b sqrt(c_b) * corr_b
__global__ void final_kernel(float* __restrict__ out) {
    __shared__ float red[32];
    float v = 0.f;
    for (int i = threadIdx.x; i < NB; i += blockDim.x)
        v += sqrtf(g_c[i]) * g_corr[i];
    float tot = block_sum(v, red);
    if (threadIdx.x == 0) out[0] = 1e-4f * (tot / (float)NB);
}

// ------------------------------------------------------------------
extern "C" void kernel_launch(void* const* d_in, const int* in_sizes, int n_in,
                              void* d_out, int out_size) {
    (void)in_sizes; (void)n_in; (void)out_size;
    const float* cores = (const float*)d_in[0];
    float* out = (float*)d_out;

    cudaFuncSetAttribute(gemm_t<1024, 0>, cudaFuncAttributeMaxDynamicSharedMemorySize, SMEM_GEMM);
    cudaFuncSetAttribute(gemm_t<256, 1>,  cudaFuncAttributeMaxDynamicSharedMemorySize, SMEM_GEMM);
    cudaFuncSetAttribute(gemm_t<256, 2>,  cudaFuncAttributeMaxDynamicSharedMemorySize, SMEM_GEMM);
    cudaFuncSetAttribute(gemm_t<256, 3>,  cudaFuncAttributeMaxDynamicSharedMemorySize, SMEM_GEMM);

    void *xt_, *gg_, *aa_, *y_, *z_, *tt_;
    cudaGetSymbolAddress(&xt_, g_Xt);
    cudaGetSymbolAddress(&gg_, g_G);
    cudaGetSymbolAddress(&aa_, g_A);
    cudaGetSymbolAddress(&y_,  g_Y);
    cudaGetSymbolAddress(&z_,  g_Z);
    cudaGetSymbolAddress(&tt_, g_T);
    const __nv_bfloat16* Xt = (const __nv_bfloat16*)xt_;
    float* G = (float*)gg_;
    const __nv_bfloat16* Ab = (const __nv_bfloat16*)aa_;
    __nv_bfloat16* Y0 = (__nv_bfloat16*)y_;
    __nv_bfloat16* Y1 = (__nv_bfloat16*)y_ + NB * MSZ;
    __nv_bfloat16* TB = (__nv_bfloat16*)z_;               // g_Z[0] reused as T buffer
    __nv_bfloat16* Z2 = (__nv_bfloat16*)z_ + NB * MSZ;    // g_Z[1]
    __nv_bfloat16* T0 = (__nv_bfloat16*)tt_;              // g_T: T0, later T2

    convert_kernel<<<dim3(KD / 64, ND / 64, NB), 256>>>(cores);

    // G = Xt * Xt^T (fp32, symmetric 3 tiles + mirror; diag tiles single-load)
    gemm_t<1024, 0><<<dim3(3, NB), 256, SMEM_GEMM>>>(Xt, Xt, G, Xt, Xt, G,
                                                     (size_t)ND * KD, (size_t)ND * KD);
    powc_kernel<<<NB, 256>>>();
    setup_kernel<<<dim3(8, NB), 256>>>();      // A, T0 (Z1 aliases T0); zero g_corr

    // Y1 = A * T0^T
    gemm_t<256, 2><<<dim3(3, NB), 256, SMEM_GEMM>>>(Ab, T0, Y1, Ab, T0, Y1, MSZ, MSZ);

    // t=0: T1 = (3I - Z1*Y1^T)/2 with Z1 = T0 (read g_T), output -> TB
    gemm_t<256, 1><<<dim3(3, NB), 256, SMEM_GEMM>>>(T0, Y1, TB, T0, Y1, TB, MSZ, MSZ);
    // t=0: Y2 = Y1*T1^T -> Y0 ; Z2 = T1*T0^T -> Z2
    gemm_t<256, 2><<<dim3(6, NB), 256, SMEM_GEMM>>>(Y1, TB, Y0, TB, T0, Z2, MSZ, MSZ);

    // t=1: T2 = (3I - Z2*Y2^T)/2 -> g_T (T0 dead)
    gemm_t<256, 1><<<dim3(3, NB), 256, SMEM_GEMM>>>(Z2, Y0, T0, Z2, Y0, T0, MSZ, MSZ);
    // t=1: Y3 = Y2*T2^T -> Y1 (Z lags at Z2; fp32 correction absorbs it)
    gemm_t<256, 2><<<dim3(3, NB), 256, SMEM_GEMM>>>(Y0, T0, Y1, Y0, T0, Y1, MSZ, MSZ);

    // corr += trY3 + 0.5*<Z2, A - Y3 Y3^T> fused into GEMM epilogue (diag single-load)
    gemm_t<256, 3><<<dim3(3, NB), 256, SMEM_GEMM>>>(Y1, Y1, Z2, Y1, Y1, Z2, MSZ, MSZ);
    final_kernel<<<1, 128>>>(out);
}